// round 1
// baseline (speedup 1.0000x reference)
#include <cuda_runtime.h>
#include <math.h>

// Problem constants
#define T_TOK 16384     // B*S = 8*2048 tokens
#define DIM   1024      // D
#define HID   2048      // H
#define NEXP  8         // E
#define TOPK  2         // K

// ---------------- scratch (device globals: allocation-free rule) -----------
__device__ int   g_counts[NEXP];
__device__ int   g_offsets[NEXP];
__device__ int   g_cursors[NEXP];
__device__ int   g_perm[T_TOK * TOPK];     // pos -> token
__device__ int   g_rowOf[T_TOK * TOPK];    // (token,slot) -> pos
__device__ int   g_sel[T_TOK * TOPK];      // (token,slot) -> expert
__device__ float g_gw[T_TOK * TOPK];       // (token,slot) -> gate weight
__device__ float g_hidden[(size_t)T_TOK * TOPK * HID];  // 256 MB
__device__ float g_y[(size_t)T_TOK * TOPK * DIM];       // 128 MB

// ---------------- kernel 0: zero counters ----------------------------------
__global__ void zero_kernel() {
    if (threadIdx.x < NEXP) g_counts[threadIdx.x] = 0;
}

// ---------------- kernel 1: gating (1 warp per token) -----------------------
__global__ void gating_kernel(const float* __restrict__ x,
                              const float* __restrict__ gw) {
    int gwarp = (blockIdx.x * blockDim.x + threadIdx.x) >> 5;
    int lane  = threadIdx.x & 31;
    if (gwarp >= T_TOK) return;
    const float* xr = x + (size_t)gwarp * DIM;

    float xv[DIM / 32];
#pragma unroll
    for (int i = 0; i < DIM / 32; i++) xv[i] = xr[lane + 32 * i];

    float logits[NEXP];
#pragma unroll
    for (int e = 0; e < NEXP; e++) {
        const float* g = gw + e * DIM;
        float acc = 0.f;
#pragma unroll
        for (int i = 0; i < DIM / 32; i++) acc = fmaf(xv[i], g[lane + 32 * i], acc);
#pragma unroll
        for (int o = 16; o; o >>= 1) acc += __shfl_xor_sync(0xffffffffu, acc, o);
        logits[e] = acc;
    }

    if (lane == 0) {
        // top-1 (lowest index wins ties, matching lax.top_k)
        int e0 = 0; float l0 = logits[0];
#pragma unroll
        for (int e = 1; e < NEXP; e++)
            if (logits[e] > l0) { l0 = logits[e]; e0 = e; }
        // top-2
        int e1 = (e0 == 0) ? 1 : 0; float l1 = logits[e1];
#pragma unroll
        for (int e = 0; e < NEXP; e++)
            if (e != e0 && logits[e] > l1) { l1 = logits[e]; e1 = e; }
        // softmax over the 2 selected (l0 >= l1)
        float p1 = __expf(l1 - l0);
        float inv = 1.f / (1.f + p1);
        g_sel[gwarp * 2 + 0] = e0;
        g_sel[gwarp * 2 + 1] = e1;
        g_gw[gwarp * 2 + 0]  = inv;
        g_gw[gwarp * 2 + 1]  = p1 * inv;
        atomicAdd(&g_counts[e0], 1);
        atomicAdd(&g_counts[e1], 1);
    }
}

// ---------------- kernel 2: scan (tiny, E=8) --------------------------------
__global__ void scan_kernel() {
    int o = 0;
    for (int e = 0; e < NEXP; e++) {
        g_offsets[e] = o;
        g_cursors[e] = o;
        o += g_counts[e];
    }
}

// ---------------- kernel 3: scatter ----------------------------------------
__global__ void scatter_kernel() {
    int idx = blockIdx.x * blockDim.x + threadIdx.x;
    if (idx >= T_TOK * TOPK) return;
    int e   = g_sel[idx];
    int pos = atomicAdd(&g_cursors[e], 1);
    g_perm[pos]  = idx >> 1;  // token index
    g_rowOf[idx] = pos;
}

// ---------------- GEMM1: hidden = silu(x@w1^T) * (x@w3^T), fused -----------
// Tile 128(M) x 64(N) x 16(K), 256 threads, per-thread 8x4 micro-tile.
__global__ __launch_bounds__(256)
void gemm1_kernel(const float* __restrict__ x,
                  const float* __restrict__ w1,
                  const float* __restrict__ w3) {
    int e    = blockIdx.z;
    int cnt  = g_counts[e];
    int row0 = blockIdx.y * 128;
    if (row0 >= cnt) return;
    int base = g_offsets[e];
    int n0   = blockIdx.x * 64;

    __shared__ __align__(16) float As[16][132];
    __shared__ __align__(16) float B1s[16][68];
    __shared__ __align__(16) float B3s[16][68];
    __shared__ int toks[128];

    int tid = threadIdx.x;
    if (tid < 128) {
        int r = row0 + tid;
        toks[tid] = (r < cnt) ? g_perm[base + r] : -1;
    }
    __syncthreads();

    const float* w1p = w1 + ((size_t)e * HID + n0) * DIM;
    const float* w3p = w3 + ((size_t)e * HID + n0) * DIM;

    float acc1[8][4], acc3[8][4];
#pragma unroll
    for (int i = 0; i < 8; i++)
#pragma unroll
        for (int j = 0; j < 4; j++) { acc1[i][j] = 0.f; acc3[i][j] = 0.f; }

    int tx = tid & 15;   // n sub-tile
    int ty = tid >> 4;   // m sub-tile

    for (int kt = 0; kt < DIM; kt += 16) {
        // A tile: 128 rows x 16 k -> 512 float4 loads, 2 per thread
#pragma unroll
        for (int it = 0; it < 2; it++) {
            int li = tid + it * 256;
            int m  = li >> 2, kq = li & 3;
            int tok = toks[m];
            float4 v = make_float4(0.f, 0.f, 0.f, 0.f);
            if (tok >= 0)
                v = *(const float4*)(x + (size_t)tok * DIM + kt + kq * 4);
            As[kq * 4 + 0][m] = v.x; As[kq * 4 + 1][m] = v.y;
            As[kq * 4 + 2][m] = v.z; As[kq * 4 + 3][m] = v.w;
        }
        // B tiles: 64 rows x 16 k each
        {
            int n = tid >> 2, kq = tid & 3;
            float4 v1 = *(const float4*)(w1p + (size_t)n * DIM + kt + kq * 4);
            float4 v3 = *(const float4*)(w3p + (size_t)n * DIM + kt + kq * 4);
            B1s[kq * 4 + 0][n] = v1.x; B1s[kq * 4 + 1][n] = v1.y;
            B1s[kq * 4 + 2][n] = v1.z; B1s[kq * 4 + 3][n] = v1.w;
            B3s[kq * 4 + 0][n] = v3.x; B3s[kq * 4 + 1][n] = v3.y;
            B3s[kq * 4 + 2][n] = v3.z; B3s[kq * 4 + 3][n] = v3.w;
        }
        __syncthreads();

#pragma unroll
        for (int k = 0; k < 16; k++) {
            float4 a0  = *(const float4*)&As[k][ty * 4];
            float4 a1  = *(const float4*)&As[k][64 + ty * 4];
            float4 b1v = *(const float4*)&B1s[k][tx * 4];
            float4 b3v = *(const float4*)&B3s[k][tx * 4];
            float a[8]  = {a0.x, a0.y, a0.z, a0.w, a1.x, a1.y, a1.z, a1.w};
            float b1a[4] = {b1v.x, b1v.y, b1v.z, b1v.w};
            float b3a[4] = {b3v.x, b3v.y, b3v.z, b3v.w};
#pragma unroll
            for (int i = 0; i < 8; i++)
#pragma unroll
                for (int j = 0; j < 4; j++) {
                    acc1[i][j] = fmaf(a[i], b1a[j], acc1[i][j]);
                    acc3[i][j] = fmaf(a[i], b3a[j], acc3[i][j]);
                }
        }
        __syncthreads();
    }

    // epilogue: silu(h1)*h3 -> hidden
#pragma unroll
    for (int i = 0; i < 8; i++) {
        int m = (i < 4) ? (ty * 4 + i) : (64 + ty * 4 + (i - 4));
        int r = row0 + m;
        if (r < cnt) {
            float* hp = g_hidden + (size_t)(base + r) * HID + n0 + tx * 4;
#pragma unroll
            for (int j = 0; j < 4; j++) {
                float h1 = acc1[i][j];
                float s  = h1 / (1.f + __expf(-h1));   // silu
                hp[j] = s * acc3[i][j];
            }
        }
    }
}

// ---------------- GEMM2: y = hidden @ w2^T ----------------------------------
__global__ __launch_bounds__(256)
void gemm2_kernel(const float* __restrict__ w2) {
    int e    = blockIdx.z;
    int cnt  = g_counts[e];
    int row0 = blockIdx.y * 128;
    if (row0 >= cnt) return;
    int base = g_offsets[e];
    int n0   = blockIdx.x * 64;

    __shared__ __align__(16) float As[16][132];
    __shared__ __align__(16) float Bs[16][68];

    int tid = threadIdx.x;
    const float* w2p = w2 + ((size_t)e * DIM + n0) * HID;

    float acc[8][4];
#pragma unroll
    for (int i = 0; i < 8; i++)
#pragma unroll
        for (int j = 0; j < 4; j++) acc[i][j] = 0.f;

    int tx = tid & 15;
    int ty = tid >> 4;

    for (int kt = 0; kt < HID; kt += 16) {
#pragma unroll
        for (int it = 0; it < 2; it++) {
            int li = tid + it * 256;
            int m  = li >> 2, kq = li & 3;
            int r  = row0 + m;
            float4 v = make_float4(0.f, 0.f, 0.f, 0.f);
            if (r < cnt)
                v = *(const float4*)(g_hidden + (size_t)(base + r) * HID + kt + kq * 4);
            As[kq * 4 + 0][m] = v.x; As[kq * 4 + 1][m] = v.y;
            As[kq * 4 + 2][m] = v.z; As[kq * 4 + 3][m] = v.w;
        }
        {
            int n = tid >> 2, kq = tid & 3;
            float4 v = *(const float4*)(w2p + (size_t)n * HID + kt + kq * 4);
            Bs[kq * 4 + 0][n] = v.x; Bs[kq * 4 + 1][n] = v.y;
            Bs[kq * 4 + 2][n] = v.z; Bs[kq * 4 + 3][n] = v.w;
        }
        __syncthreads();

#pragma unroll
        for (int k = 0; k < 16; k++) {
            float4 a0 = *(const float4*)&As[k][ty * 4];
            float4 a1 = *(const float4*)&As[k][64 + ty * 4];
            float4 bv = *(const float4*)&Bs[k][tx * 4];
            float a[8]  = {a0.x, a0.y, a0.z, a0.w, a1.x, a1.y, a1.z, a1.w};
            float b[4]  = {bv.x, bv.y, bv.z, bv.w};
#pragma unroll
            for (int i = 0; i < 8; i++)
#pragma unroll
                for (int j = 0; j < 4; j++)
                    acc[i][j] = fmaf(a[i], b[j], acc[i][j]);
        }
        __syncthreads();
    }

#pragma unroll
    for (int i = 0; i < 8; i++) {
        int m = (i < 4) ? (ty * 4 + i) : (64 + ty * 4 + (i - 4));
        int r = row0 + m;
        if (r < cnt) {
            float* yp = g_y + (size_t)(base + r) * DIM + n0 + tx * 4;
#pragma unroll
            for (int j = 0; j < 4; j++) yp[j] = acc[i][j];
        }
    }
}

// ---------------- combine: out[t] = w0*y[row0] + w1*y[row1] -----------------
__global__ void combine_kernel(float* __restrict__ out) {
    int idx = blockIdx.x * blockDim.x + threadIdx.x;   // over T*D/4
    if (idx >= T_TOK * DIM / 4) return;
    int t  = idx / (DIM / 4);
    int d4 = idx - t * (DIM / 4);
    float w0 = g_gw[t * 2 + 0], w1 = g_gw[t * 2 + 1];
    const float4 y0 = *(const float4*)(g_y + (size_t)g_rowOf[t * 2 + 0] * DIM + d4 * 4);
    const float4 y1 = *(const float4*)(g_y + (size_t)g_rowOf[t * 2 + 1] * DIM + d4 * 4);
    float4 o;
    o.x = w0 * y0.x + w1 * y1.x;
    o.y = w0 * y0.y + w1 * y1.y;
    o.z = w0 * y0.z + w1 * y1.z;
    o.w = w0 * y0.w + w1 * y1.w;
    ((float4*)out)[idx] = o;
}

// ---------------- launch ----------------------------------------------------
extern "C" void kernel_launch(void* const* d_in, const int* in_sizes, int n_in,
                              void* d_out, int out_size) {
    const float* x   = (const float*)d_in[0];
    const float* gw  = (const float*)d_in[1];
    const float* w1  = (const float*)d_in[2];
    const float* w3  = (const float*)d_in[3];
    const float* w2  = (const float*)d_in[4];
    float* out = (float*)d_out;

    zero_kernel<<<1, 32>>>();
    gating_kernel<<<T_TOK / 8, 256>>>(x, gw);
    scan_kernel<<<1, 1>>>();
    scatter_kernel<<<(T_TOK * TOPK + 255) / 256, 256>>>();

    dim3 g1(HID / 64, T_TOK / 128, NEXP);
    gemm1_kernel<<<g1, 256>>>(x, w1, w3);

    dim3 g2(DIM / 64, T_TOK / 128, NEXP);
    gemm2_kernel<<<g2, 256>>>(w2);

    combine_kernel<<<(T_TOK * DIM / 4 + 255) / 256, 256>>>(out);
}

// round 3
// speedup vs baseline: 2.0028x; 2.0028x over previous
#include <cuda_runtime.h>
#include <cuda_bf16.h>
#include <math.h>
#include <stdint.h>

// ---------------- problem constants ----------------
#define T_TOK 16384
#define DIM   1024
#define HID   2048
#define NEXP  8
#define TOPK  2
#define NSLOT (T_TOK*TOPK)                 // 32768
#define PADT  (NSLOT + NEXP*128)           // 33792 padded rows

typedef __nv_bfloat16 bf16;

// ---------------- device scratch (allocation-free rule) ----------------
__device__ int   g_counts[NEXP];
__device__ int   g_cntpad[NEXP];
__device__ int   g_offsets[NEXP];
__device__ int   g_cursors[NEXP];
__device__ int   g_perm[PADT];
__device__ int   g_rowOf[NSLOT];
__device__ int   g_sel[NSLOT];
__device__ float g_gwt[NSLOT];

__device__ bf16  g_w1h[(size_t)NEXP*HID*DIM];
__device__ bf16  g_w1l[(size_t)NEXP*HID*DIM];
__device__ bf16  g_w3h[(size_t)NEXP*HID*DIM];
__device__ bf16  g_w3l[(size_t)NEXP*HID*DIM];
__device__ bf16  g_w2h[(size_t)NEXP*DIM*HID];
__device__ bf16  g_w2l[(size_t)NEXP*DIM*HID];
__device__ bf16  g_xh[(size_t)PADT*DIM];
__device__ bf16  g_xl[(size_t)PADT*DIM];
__device__ bf16  g_hh[(size_t)PADT*HID];
__device__ bf16  g_hl[(size_t)PADT*HID];
__device__ float g_y [(size_t)PADT*DIM];

// ---------------- helpers (base-PTX only) ----------------
__device__ __forceinline__ uint32_t smem_u32(const void* p) {
    uint32_t a;
    asm("{ .reg .u64 t; cvta.to.shared.u64 t, %1; cvt.u32.u64 %0, t; }" : "=r"(a) : "l"(p));
    return a;
}
__device__ __forceinline__ void cp16(uint32_t dst, const void* src) {
    asm volatile("cp.async.cg.shared.global [%0], [%1], 16;" :: "r"(dst), "l"(src));
}
__device__ __forceinline__ void cp_commit() {
    asm volatile("cp.async.commit_group;");
}
__device__ __forceinline__ void cp_wait0() {
    asm volatile("cp.async.wait_group 0;" ::: "memory");
}
__device__ __forceinline__ void cp_wait1() {
    asm volatile("cp.async.wait_group 1;" ::: "memory");
}
// m16n8k16 row.col bf16 -> f32 accum (base PTX, HMMA pipe)
__device__ __forceinline__ void mma_bf16(float c[4], uint32_t a0, uint32_t a1,
                                         uint32_t a2, uint32_t a3,
                                         uint32_t b0, uint32_t b1) {
    asm volatile(
        "mma.sync.aligned.m16n8k16.row.col.f32.bf16.bf16.f32 "
        "{%0,%1,%2,%3}, {%4,%5,%6,%7}, {%8,%9}, {%0,%1,%2,%3};"
        : "+f"(c[0]), "+f"(c[1]), "+f"(c[2]), "+f"(c[3])
        : "r"(a0), "r"(a1), "r"(a2), "r"(a3), "r"(b0), "r"(b1));
}

// ---------------- kernel: weight convert (+ zero counters) ----------------
#define WQ ((size_t)NEXP*HID*DIM/4)
__global__ __launch_bounds__(256) void wconv_kernel(const float* __restrict__ w1,
                                                    const float* __restrict__ w3,
                                                    const float* __restrict__ w2) {
    if (blockIdx.x == 0 && threadIdx.x < NEXP) g_counts[threadIdx.x] = 0;
    size_t i = (size_t)blockIdx.x * blockDim.x + threadIdx.x;
    if (i >= 3 * WQ) return;
    const float* src; bf16 *hi, *lo; size_t j;
    if (i < WQ)           { src = w1; hi = g_w1h; lo = g_w1l; j = i; }
    else if (i < 2 * WQ)  { src = w3; hi = g_w3h; lo = g_w3l; j = i - WQ; }
    else                  { src = w2; hi = g_w2h; lo = g_w2l; j = i - 2 * WQ; }
    float4 v = ((const float4*)src)[j];
    __nv_bfloat162 h0, h1, l0, l1;
    h0.x = __float2bfloat16(v.x); h0.y = __float2bfloat16(v.y);
    h1.x = __float2bfloat16(v.z); h1.y = __float2bfloat16(v.w);
    l0.x = __float2bfloat16(v.x - __bfloat162float(h0.x));
    l0.y = __float2bfloat16(v.y - __bfloat162float(h0.y));
    l1.x = __float2bfloat16(v.z - __bfloat162float(h1.x));
    l1.y = __float2bfloat16(v.w - __bfloat162float(h1.y));
    ((__nv_bfloat162*)(hi + 4 * j))[0] = h0;
    ((__nv_bfloat162*)(hi + 4 * j))[1] = h1;
    ((__nv_bfloat162*)(lo + 4 * j))[0] = l0;
    ((__nv_bfloat162*)(lo + 4 * j))[1] = l1;
}

// ---------------- gating (1 warp / token) ----------------
__global__ void gating_kernel(const float* __restrict__ x, const float* __restrict__ gw) {
    int t = (blockIdx.x * blockDim.x + threadIdx.x) >> 5;
    int lane = threadIdx.x & 31;
    if (t >= T_TOK) return;
    const float* xr = x + (size_t)t * DIM;
    float xv[DIM / 32];
#pragma unroll
    for (int i = 0; i < DIM / 32; i++) xv[i] = xr[lane + 32 * i];
    float logits[NEXP];
#pragma unroll
    for (int e = 0; e < NEXP; e++) {
        const float* g = gw + e * DIM;
        float acc = 0.f;
#pragma unroll
        for (int i = 0; i < DIM / 32; i++) acc = fmaf(xv[i], g[lane + 32 * i], acc);
#pragma unroll
        for (int o = 16; o; o >>= 1) acc += __shfl_xor_sync(0xffffffffu, acc, o);
        logits[e] = acc;
    }
    if (lane == 0) {
        int e0 = 0; float l0 = logits[0];
#pragma unroll
        for (int e = 1; e < NEXP; e++) if (logits[e] > l0) { l0 = logits[e]; e0 = e; }
        int e1 = (e0 == 0) ? 1 : 0; float l1 = logits[e1];
#pragma unroll
        for (int e = 0; e < NEXP; e++) if (e != e0 && logits[e] > l1) { l1 = logits[e]; e1 = e; }
        float p1 = __expf(l1 - l0);
        float inv = 1.f / (1.f + p1);
        g_sel[t * 2 + 0] = e0; g_sel[t * 2 + 1] = e1;
        g_gwt[t * 2 + 0] = inv; g_gwt[t * 2 + 1] = p1 * inv;
        atomicAdd(&g_counts[e0], 1);
        atomicAdd(&g_counts[e1], 1);
    }
}

// ---------------- scan ----------------
__global__ void scan_kernel() {
    int o = 0;
    for (int e = 0; e < NEXP; e++) {
        int c = g_counts[e];
        int cp = (c + 127) & ~127;
        g_offsets[e] = o; g_cursors[e] = o; g_cntpad[e] = cp;
        o += cp;
    }
}

// ---------------- scatter ----------------
__global__ void scatter_kernel() {
    int idx = blockIdx.x * blockDim.x + threadIdx.x;
    if (idx >= NSLOT) return;
    int e = g_sel[idx];
    int pos = atomicAdd(&g_cursors[e], 1);
    g_perm[pos] = idx >> 1;
    g_rowOf[idx] = pos;
}

// ---------------- gather + convert x -> padded bf16 hi/lo ----------------
__global__ __launch_bounds__(256) void gather_kernel(const float* __restrict__ x) {
    int row = blockIdx.x;
    int e = -1, r = 0;
#pragma unroll
    for (int i = 0; i < NEXP; i++) {
        int o = g_offsets[i], c = g_cntpad[i];
        if (row >= o && row < o + c) { e = i; r = row - o; }
    }
    if (e < 0) return;
    float4 v = make_float4(0.f, 0.f, 0.f, 0.f);
    if (r < g_counts[e]) {
        int tok = g_perm[row];
        v = *(const float4*)(x + (size_t)tok * DIM + threadIdx.x * 4);
    }
    size_t o = (size_t)row * DIM + threadIdx.x * 4;
    __nv_bfloat162 h0, h1, l0, l1;
    h0.x = __float2bfloat16(v.x); h0.y = __float2bfloat16(v.y);
    h1.x = __float2bfloat16(v.z); h1.y = __float2bfloat16(v.w);
    l0.x = __float2bfloat16(v.x - __bfloat162float(h0.x));
    l0.y = __float2bfloat16(v.y - __bfloat162float(h0.y));
    l1.x = __float2bfloat16(v.z - __bfloat162float(h1.x));
    l1.y = __float2bfloat16(v.w - __bfloat162float(h1.y));
    ((__nv_bfloat162*)(g_xh + o))[0] = h0; ((__nv_bfloat162*)(g_xh + o))[1] = h1;
    ((__nv_bfloat162*)(g_xl + o))[0] = l0; ((__nv_bfloat162*)(g_xl + o))[1] = l1;
}

// ---------------- shared memory layouts ----------------
// Row stride 40 halves = 80 bytes: 16B-aligned, conflict-free across 8 rows.
#define SAW 80
// GEMM1 stage: A hi/lo [128x32], B1 hi/lo [64x32], B3 hi/lo [64x32]
#define G1_AH  0
#define G1_AL  10240
#define G1_B1H 20480
#define G1_B1L 25600
#define G1_B3H 30720
#define G1_B3L 35840
#define G1_STAGE 40960
#define G1_SMEM (2*G1_STAGE)
// GEMM2 stage: A hi/lo [128x32], B hi/lo [128x32]
#define G2_AH  0
#define G2_AL  10240
#define G2_BH  20480
#define G2_BL  30720
#define G2_STAGE 40960
#define G2_SMEM (2*G2_STAGE)

// ---------------- GEMM1: hidden = silu(x@w1^T) * (x@w3^T) -------------------
// CTA tile 128(M) x 64(N), both outputs; K-chunk 32; bf16x3.
__device__ __forceinline__ void g1_load(uint32_t st,
        const bf16* Ah, const bf16* Al,
        const bf16* B1h, const bf16* B1l,
        const bf16* B3h, const bf16* B3l, int kt, int tid) {
#pragma unroll
    for (int i = 0; i < 2; i++) {
        int idx = tid + i * 256;
        int m = idx >> 2, c = idx & 3;
        cp16(st + G1_AH + m * SAW + c * 16, Ah + (size_t)m * DIM + kt + c * 8);
        cp16(st + G1_AL + m * SAW + c * 16, Al + (size_t)m * DIM + kt + c * 8);
    }
    {
        int n = tid >> 2, c = tid & 3;
        cp16(st + G1_B1H + n * SAW + c * 16, B1h + (size_t)n * DIM + kt + c * 8);
        cp16(st + G1_B1L + n * SAW + c * 16, B1l + (size_t)n * DIM + kt + c * 8);
        cp16(st + G1_B3H + n * SAW + c * 16, B3h + (size_t)n * DIM + kt + c * 8);
        cp16(st + G1_B3L + n * SAW + c * 16, B3l + (size_t)n * DIM + kt + c * 8);
    }
}

__global__ __launch_bounds__(256, 1) void gemm1_mma() {
    int e = blockIdx.z;
    int m0blk = blockIdx.y * 128;
    if (m0blk >= g_cntpad[e]) return;
    int row0 = g_offsets[e] + m0blk;
    int n0 = blockIdx.x * 64;

    extern __shared__ __align__(16) char smem[];
    uint32_t sb = smem_u32(smem);
    int tid = threadIdx.x, lane = tid & 31, warp = tid >> 5;
    int gr = lane >> 2, gc2 = (lane & 3) * 2;
    int wm = (warp & 3) * 32;          // 4 warps along M
    int wn = (warp >> 2) * 32;         // 2 warps along N

    const bf16* Ah  = g_xh  + (size_t)row0 * DIM;
    const bf16* Al  = g_xl  + (size_t)row0 * DIM;
    const size_t wb = ((size_t)e * HID + n0) * DIM;
    const bf16* B1h = g_w1h + wb;
    const bf16* B1l = g_w1l + wb;
    const bf16* B3h = g_w3h + wb;
    const bf16* B3l = g_w3l + wb;

    float acc1[2][4][4], acc3[2][4][4];
#pragma unroll
    for (int i = 0; i < 2; i++)
#pragma unroll
        for (int j = 0; j < 4; j++)
#pragma unroll
            for (int q = 0; q < 4; q++) { acc1[i][j][q] = 0.f; acc3[i][j][q] = 0.f; }

    const int NK = DIM / 32;   // 32
    g1_load(sb, Ah, Al, B1h, B1l, B3h, B3l, 0, tid);
    cp_commit();

#pragma unroll 1
    for (int kc = 0; kc < NK; kc++) {
        if (kc + 1 < NK) {
            g1_load(sb + ((kc + 1) & 1) * G1_STAGE, Ah, Al, B1h, B1l, B3h, B3l,
                    (kc + 1) * 32, tid);
            cp_commit();
            cp_wait1();
        } else {
            cp_wait0();
        }
        __syncthreads();
        const char* st = smem + (kc & 1) * G1_STAGE;
#pragma unroll
        for (int p = 0; p < 3; p++) {
            const char* aB  = st + (p == 2 ? G1_AL  : G1_AH);
            const char* b1B = st + (p == 1 ? G1_B1L : G1_B1H);
            const char* b3B = st + (p == 1 ? G1_B3L : G1_B3H);
#pragma unroll
            for (int ks = 0; ks < 2; ks++) {
                int k0 = ks * 16;
                uint32_t a[2][4];
#pragma unroll
                for (int i = 0; i < 2; i++) {
                    const char* ab = aB + (wm + i * 16 + gr) * SAW + (k0 + gc2) * 2;
                    a[i][0] = *(const uint32_t*)ab;
                    a[i][1] = *(const uint32_t*)(ab + 8 * SAW);
                    a[i][2] = *(const uint32_t*)(ab + 16);
                    a[i][3] = *(const uint32_t*)(ab + 8 * SAW + 16);
                }
#pragma unroll
                for (int j = 0; j < 4; j++) {
                    const char* bb1 = b1B + (wn + j * 8 + gr) * SAW + (k0 + gc2) * 2;
                    const char* bb3 = b3B + (wn + j * 8 + gr) * SAW + (k0 + gc2) * 2;
                    uint32_t b10 = *(const uint32_t*)bb1, b11 = *(const uint32_t*)(bb1 + 16);
                    uint32_t b30 = *(const uint32_t*)bb3, b31 = *(const uint32_t*)(bb3 + 16);
#pragma unroll
                    for (int i = 0; i < 2; i++) {
                        mma_bf16(acc1[i][j], a[i][0], a[i][1], a[i][2], a[i][3], b10, b11);
                        mma_bf16(acc3[i][j], a[i][0], a[i][1], a[i][2], a[i][3], b30, b31);
                    }
                }
            }
        }
        __syncthreads();
    }

    // epilogue: silu(h1)*h3 -> bf16 hi/lo
#pragma unroll
    for (int i = 0; i < 2; i++)
#pragma unroll
        for (int j = 0; j < 4; j++) {
            int m = wm + i * 16 + gr;
            int n = wn + j * 8 + gc2;
#pragma unroll
            for (int half = 0; half < 2; half++) {
                int mm = m + half * 8;
                float h1a = acc1[i][j][half * 2 + 0], h1b = acc1[i][j][half * 2 + 1];
                float h3a = acc3[i][j][half * 2 + 0], h3b = acc3[i][j][half * 2 + 1];
                float v0 = h3a * h1a / (1.f + __expf(-h1a));
                float v1 = h3b * h1b / (1.f + __expf(-h1b));
                size_t idx = (size_t)(row0 + mm) * HID + n0 + n;
                __nv_bfloat162 hh, ll;
                hh.x = __float2bfloat16(v0); hh.y = __float2bfloat16(v1);
                ll.x = __float2bfloat16(v0 - __bfloat162float(hh.x));
                ll.y = __float2bfloat16(v1 - __bfloat162float(hh.y));
                *(__nv_bfloat162*)(g_hh + idx) = hh;
                *(__nv_bfloat162*)(g_hl + idx) = ll;
            }
        }
}

// ---------------- GEMM2: y = hidden @ w2^T ----------------------------------
// CTA tile 128(M) x 128(N); K-chunk 32; bf16x3.
__device__ __forceinline__ void g2_load(uint32_t st,
        const bf16* Ah, const bf16* Al,
        const bf16* Bh, const bf16* Bl, int kt, int tid) {
#pragma unroll
    for (int i = 0; i < 2; i++) {
        int idx = tid + i * 256;
        int m = idx >> 2, c = idx & 3;
        cp16(st + G2_AH + m * SAW + c * 16, Ah + (size_t)m * HID + kt + c * 8);
        cp16(st + G2_AL + m * SAW + c * 16, Al + (size_t)m * HID + kt + c * 8);
        cp16(st + G2_BH + m * SAW + c * 16, Bh + (size_t)m * HID + kt + c * 8);
        cp16(st + G2_BL + m * SAW + c * 16, Bl + (size_t)m * HID + kt + c * 8);
    }
}

__global__ __launch_bounds__(256, 1) void gemm2_mma() {
    int e = blockIdx.z;
    int m0blk = blockIdx.y * 128;
    if (m0blk >= g_cntpad[e]) return;
    int row0 = g_offsets[e] + m0blk;
    int n0 = blockIdx.x * 128;

    extern __shared__ __align__(16) char smem[];
    uint32_t sb = smem_u32(smem);
    int tid = threadIdx.x, lane = tid & 31, warp = tid >> 5;
    int gr = lane >> 2, gc2 = (lane & 3) * 2;
    int wm = (warp & 3) * 32;          // 4 warps along M
    int wn = (warp >> 2) * 64;         // 2 warps along N (64 each)

    const bf16* Ah = g_hh + (size_t)row0 * HID;
    const bf16* Al = g_hl + (size_t)row0 * HID;
    const size_t wb = ((size_t)e * DIM + n0) * HID;
    const bf16* Bh = g_w2h + wb;
    const bf16* Bl = g_w2l + wb;

    float acc[2][8][4];
#pragma unroll
    for (int i = 0; i < 2; i++)
#pragma unroll
        for (int j = 0; j < 8; j++)
#pragma unroll
            for (int q = 0; q < 4; q++) acc[i][j][q] = 0.f;

    const int NK = HID / 32;   // 64
    g2_load(sb, Ah, Al, Bh, Bl, 0, tid);
    cp_commit();

#pragma unroll 1
    for (int kc = 0; kc < NK; kc++) {
        if (kc + 1 < NK) {
            g2_load(sb + ((kc + 1) & 1) * G2_STAGE, Ah, Al, Bh, Bl, (kc + 1) * 32, tid);
            cp_commit();
            cp_wait1();
        } else {
            cp_wait0();
        }
        __syncthreads();
        const char* st = smem + (kc & 1) * G2_STAGE;
#pragma unroll
        for (int p = 0; p < 3; p++) {
            const char* aB = st + (p == 2 ? G2_AL : G2_AH);
            const char* bB = st + (p == 1 ? G2_BL : G2_BH);
#pragma unroll
            for (int ks = 0; ks < 2; ks++) {
                int k0 = ks * 16;
                uint32_t a[2][4];
#pragma unroll
                for (int i = 0; i < 2; i++) {
                    const char* ab = aB + (wm + i * 16 + gr) * SAW + (k0 + gc2) * 2;
                    a[i][0] = *(const uint32_t*)ab;
                    a[i][1] = *(const uint32_t*)(ab + 8 * SAW);
                    a[i][2] = *(const uint32_t*)(ab + 16);
                    a[i][3] = *(const uint32_t*)(ab + 8 * SAW + 16);
                }
#pragma unroll
                for (int j = 0; j < 8; j++) {
                    const char* bb = bB + (wn + j * 8 + gr) * SAW + (k0 + gc2) * 2;
                    uint32_t b0 = *(const uint32_t*)bb, b1 = *(const uint32_t*)(bb + 16);
#pragma unroll
                    for (int i = 0; i < 2; i++)
                        mma_bf16(acc[i][j], a[i][0], a[i][1], a[i][2], a[i][3], b0, b1);
                }
            }
        }
        __syncthreads();
    }

#pragma unroll
    for (int i = 0; i < 2; i++)
#pragma unroll
        for (int j = 0; j < 8; j++) {
            int m = wm + i * 16 + gr;
            int n = wn + j * 8 + gc2;
#pragma unroll
            for (int half = 0; half < 2; half++) {
                int mm = m + half * 8;
                float2 v = make_float2(acc[i][j][half * 2 + 0], acc[i][j][half * 2 + 1]);
                *(float2*)(g_y + (size_t)(row0 + mm) * DIM + n0 + n) = v;
            }
        }
}

// ---------------- combine ----------------
__global__ void combine_kernel(float* __restrict__ out) {
    int idx = blockIdx.x * blockDim.x + threadIdx.x;
    if (idx >= T_TOK * DIM / 4) return;
    int t = idx / (DIM / 4);
    int d4 = idx - t * (DIM / 4);
    float w0 = g_gwt[t * 2 + 0], w1 = g_gwt[t * 2 + 1];
    const float4 y0 = *(const float4*)(g_y + (size_t)g_rowOf[t * 2 + 0] * DIM + d4 * 4);
    const float4 y1 = *(const float4*)(g_y + (size_t)g_rowOf[t * 2 + 1] * DIM + d4 * 4);
    float4 o;
    o.x = w0 * y0.x + w1 * y1.x;
    o.y = w0 * y0.y + w1 * y1.y;
    o.z = w0 * y0.z + w1 * y1.z;
    o.w = w0 * y0.w + w1 * y1.w;
    ((float4*)out)[idx] = o;
}

// ---------------- launch ----------------
extern "C" void kernel_launch(void* const* d_in, const int* in_sizes, int n_in,
                              void* d_out, int out_size) {
    const float* x  = (const float*)d_in[0];
    const float* gw = (const float*)d_in[1];
    const float* w1 = (const float*)d_in[2];
    const float* w3 = (const float*)d_in[3];
    const float* w2 = (const float*)d_in[4];
    float* out = (float*)d_out;

    static int attr_done = 0;
    if (!attr_done) {
        cudaFuncSetAttribute(gemm1_mma, cudaFuncAttributeMaxDynamicSharedMemorySize, G1_SMEM);
        cudaFuncSetAttribute(gemm2_mma, cudaFuncAttributeMaxDynamicSharedMemorySize, G2_SMEM);
        attr_done = 1;
    }

    size_t nq = 3 * WQ;
    wconv_kernel<<<(unsigned)((nq + 255) / 256), 256>>>(w1, w3, w2);   // 0
    gating_kernel<<<T_TOK / 8, 256>>>(x, gw);                          // 1
    scan_kernel<<<1, 1>>>();                                           // 2
    scatter_kernel<<<(NSLOT + 255) / 256, 256>>>();                    // 3
    gather_kernel<<<PADT, 256>>>(x);                                   // 4
    gemm1_mma<<<dim3(HID / 64, 128, NEXP), 256, G1_SMEM>>>();          // 5  (ncu -s 5)
    gemm2_mma<<<dim3(DIM / 128, 128, NEXP), 256, G2_SMEM>>>();         // 6
    combine_kernel<<<(T_TOK * DIM / 4 + 255) / 256, 256>>>(out);       // 7
}